// round 2
// baseline (speedup 1.0000x reference)
#include <cuda_runtime.h>

#define BATCH 4
#define SEQ 2048
#define DIM 1024
#define HEADS 16
#define DHEAD 64
#define INNER 1024
#define TOKENS (BATCH * SEQ)
#define ATT_SCALE 0.125f

// Scratch (allocation-free): q, k, v, attention output. 32 MB each.
__device__ float g_q[TOKENS * INNER];
__device__ float g_k[TOKENS * INNER];
__device__ float g_v[TOKENS * INNER];
__device__ float g_o[TOKENS * INNER];

// ---------------------------------------------------------------------------
// Tiled fp32 GEMM: C = A[M,K] @ B[K,N] (+bias). Output columns < splitN go to
// C0 (ld = splitN), columns >= splitN go to C1 (ld = N - splitN).
// BM=BN=128, BK=16, 256 threads, 8x8 microtile per thread.
// All problem dims here are multiples of the tiles -> no bounds checks.
// ---------------------------------------------------------------------------
#define GBM 128
#define GBN 128
#define GBK 16

__global__ __launch_bounds__(256, 2)
void gemm_kernel(const float* __restrict__ A, const float* __restrict__ B,
                 float* __restrict__ C0, float* __restrict__ C1,
                 int splitN, const float* __restrict__ bias,
                 int N, int K)
{
    __shared__ float As[GBK][GBM];   // A tile, transposed: As[k][m]
    __shared__ float Bs[GBK][GBN];   // B tile, natural:    Bs[k][n]

    const int m0  = blockIdx.y * GBM;
    const int n0  = blockIdx.x * GBN;
    const int tid = threadIdx.x;
    const int ty  = tid >> 4;        // 0..15 -> row group
    const int tx  = tid & 15;        // 0..15 -> col group

    // A-tile load mapping: 2 float4 per thread
    const int arow = tid >> 2;           // 0..63
    const int acol = (tid & 3) << 2;     // 0,4,8,12
    // B-tile load mapping: 2 float4 per thread (fully coalesced)
    const int brow = tid >> 5;           // 0..7
    const int bcol = (tid & 31) << 2;    // 0..124

    const float* Ap = A + m0 * K;
    const float* Bp = B + n0;

    float acc[8][8];
#pragma unroll
    for (int i = 0; i < 8; i++)
#pragma unroll
        for (int j = 0; j < 8; j++) acc[i][j] = 0.f;

    for (int k0 = 0; k0 < K; k0 += GBK) {
        float4 a0 = *(const float4*)(Ap + arow * K + k0 + acol);
        float4 a1 = *(const float4*)(Ap + (arow + 64) * K + k0 + acol);
        float4 b0 = *(const float4*)(Bp + (k0 + brow) * N + bcol);
        float4 b1 = *(const float4*)(Bp + (k0 + brow + 8) * N + bcol);
        __syncthreads();   // previous iteration's smem reads done
        As[acol + 0][arow] = a0.x;
        As[acol + 1][arow] = a0.y;
        As[acol + 2][arow] = a0.z;
        As[acol + 3][arow] = a0.w;
        As[acol + 0][arow + 64] = a1.x;
        As[acol + 1][arow + 64] = a1.y;
        As[acol + 2][arow + 64] = a1.z;
        As[acol + 3][arow + 64] = a1.w;
        *(float4*)&Bs[brow][bcol]     = b0;
        *(float4*)&Bs[brow + 8][bcol] = b1;
        __syncthreads();

#pragma unroll
        for (int k = 0; k < GBK; k++) {
            float av[8], bv[8];
            *(float4*)&av[0] = *(const float4*)&As[k][ty * 8];
            *(float4*)&av[4] = *(const float4*)&As[k][ty * 8 + 4];
            *(float4*)&bv[0] = *(const float4*)&Bs[k][tx * 8];
            *(float4*)&bv[4] = *(const float4*)&Bs[k][tx * 8 + 4];
#pragma unroll
            for (int i = 0; i < 8; i++)
#pragma unroll
                for (int j = 0; j < 8; j++)
                    acc[i][j] = fmaf(av[i], bv[j], acc[i][j]);
        }
    }

    // Epilogue: whole 128-wide block lands on one side of the split
    float* Cb;
    int ldc, c0;
    if (n0 < splitN) { Cb = C0; ldc = splitN;     c0 = n0; }
    else             { Cb = C1; ldc = N - splitN; c0 = n0 - splitN; }

#pragma unroll
    for (int i = 0; i < 8; i++) {
        int row = m0 + ty * 8 + i;
#pragma unroll
        for (int j = 0; j < 8; j += 4) {
            float4 r;
            r.x = acc[i][j];     r.y = acc[i][j + 1];
            r.z = acc[i][j + 2]; r.w = acc[i][j + 3];
            if (bias) {
                int gc = n0 + tx * 8 + j;
                r.x += bias[gc];     r.y += bias[gc + 1];
                r.z += bias[gc + 2]; r.w += bias[gc + 3];
            }
            *(float4*)(Cb + row * ldc + c0 + tx * 8 + j) = r;
        }
    }
}

// ---------------------------------------------------------------------------
// Flash attention, fp32. One block = 64 query rows of one (batch, head).
// 256 threads as a 16x16 grid; each thread owns a 4x4 microtile of the 64x64
// S tile and a 4x4 microtile (rows x dims) of the 64x64 O accumulator.
// Smem: Qs (Q^T, swizzled), KPs (K^T swizzled, reused for P^T swizzled),
// Vs (natural). 3 x 16 KB = 48 KB static.
// Swizzle: element (r, c) of a logically-transposed [64][64] tile lives at
// physical column ((c>>2) ^ (r>>2))*4 + (c&3)  -> all compute-phase vector
// LDS are conflict-free; transpose stores are ~2-4 way instead of 16-way.
// ---------------------------------------------------------------------------
__global__ __launch_bounds__(256, 2)
void flash_kernel(const float* __restrict__ Q, const float* __restrict__ Kg,
                  const float* __restrict__ Vg, float* __restrict__ O)
{
    __shared__ float Qs[64][64];    // Q^T : [d][row] swizzled
    __shared__ float KPs[64][64];   // K^T : [d][col] swizzled, then P^T : [col][row]
    __shared__ float Vs[64][64];    // V   : [col][d] natural

    const int bh  = blockIdx.y;
    const int b   = bh >> 4;
    const int h   = bh & 15;
    const int qt  = blockIdx.x;
    const int tid = threadIdx.x;
    const int ty  = tid >> 4;   // row group (S rows & O rows)
    const int tx  = tid & 15;   // col group (S cols / O dims)

    const float* qb = Q  + (b * SEQ + qt * 64) * INNER + h * DHEAD;
    const float* kb = Kg + b * SEQ * INNER + h * DHEAD;
    const float* vb = Vg + b * SEQ * INNER + h * DHEAD;

    // Load Q tile transposed + swizzled
#pragma unroll
    for (int rep = 0; rep < 4; rep++) {
        int f   = tid + rep * 256;
        int row = f >> 4;
        int d4  = f & 15;
        float4 v = *(const float4*)(qb + row * INNER + d4 * 4);
        int pc = (((row >> 2) ^ d4) << 2) + (row & 3);
        Qs[d4 * 4 + 0][pc] = v.x;
        Qs[d4 * 4 + 1][pc] = v.y;
        Qs[d4 * 4 + 2][pc] = v.z;
        Qs[d4 * 4 + 3][pc] = v.w;
    }

    float acc[4][4];
    float m[4], l[4];
#pragma unroll
    for (int i = 0; i < 4; i++) {
        m[i] = -1e30f; l[i] = 0.f;
#pragma unroll
        for (int j = 0; j < 4; j++) acc[i][j] = 0.f;
    }

    for (int kb0 = 0; kb0 < SEQ / 64; kb0++) {
        __syncthreads();   // previous iteration's P/V reads done
        const float* kp = kb + kb0 * 64 * INNER;
        const float* vp = vb + kb0 * 64 * INNER;
#pragma unroll
        for (int rep = 0; rep < 4; rep++) {
            int f   = tid + rep * 256;
            int row = f >> 4;
            int d4  = f & 15;
            float4 kv = *(const float4*)(kp + row * INNER + d4 * 4);
            int pc = (((row >> 2) ^ d4) << 2) + (row & 3);
            KPs[d4 * 4 + 0][pc] = kv.x;
            KPs[d4 * 4 + 1][pc] = kv.y;
            KPs[d4 * 4 + 2][pc] = kv.z;
            KPs[d4 * 4 + 3][pc] = kv.w;
            float4 vv = *(const float4*)(vp + row * INNER + d4 * 4);
            *(float4*)&Vs[row][d4 * 4] = vv;
        }
        __syncthreads();

        // S = Q @ K^T (4x4 per thread)
        float s[4][4];
#pragma unroll
        for (int i = 0; i < 4; i++)
#pragma unroll
            for (int j = 0; j < 4; j++) s[i][j] = 0.f;
#pragma unroll 8
        for (int kd = 0; kd < 64; kd++) {
            float4 a = *(const float4*)&Qs[kd][(ty ^ (kd >> 2)) << 2];
            float4 c = *(const float4*)&KPs[kd][(tx ^ (kd >> 2)) << 2];
            float av[4] = {a.x, a.y, a.z, a.w};
            float cv[4] = {c.x, c.y, c.z, c.w};
#pragma unroll
            for (int i = 0; i < 4; i++)
#pragma unroll
                for (int j = 0; j < 4; j++)
                    s[i][j] = fmaf(av[i], cv[j], s[i][j]);
        }

        // Online softmax (row stats reduced over the 16 lanes sharing a row)
        float p[4][4];
#pragma unroll
        for (int i = 0; i < 4; i++) {
            float rm = -1e30f;
#pragma unroll
            for (int j = 0; j < 4; j++) {
                s[i][j] *= ATT_SCALE;
                rm = fmaxf(rm, s[i][j]);
            }
            rm = fmaxf(rm, __shfl_xor_sync(0xffffffffu, rm, 8));
            rm = fmaxf(rm, __shfl_xor_sync(0xffffffffu, rm, 4));
            rm = fmaxf(rm, __shfl_xor_sync(0xffffffffu, rm, 2));
            rm = fmaxf(rm, __shfl_xor_sync(0xffffffffu, rm, 1));
            float mn    = fmaxf(m[i], rm);
            float alpha = __expf(m[i] - mn);
            m[i] = mn;
            float rs = 0.f;
#pragma unroll
            for (int j = 0; j < 4; j++) {
                p[i][j] = __expf(s[i][j] - mn);
                rs += p[i][j];
            }
            rs += __shfl_xor_sync(0xffffffffu, rs, 8);
            rs += __shfl_xor_sync(0xffffffffu, rs, 4);
            rs += __shfl_xor_sync(0xffffffffu, rs, 2);
            rs += __shfl_xor_sync(0xffffffffu, rs, 1);
            l[i] = l[i] * alpha + rs;
#pragma unroll
            for (int j = 0; j < 4; j++) acc[i][j] *= alpha;
        }

        __syncthreads();   // done reading KPs as K
        // Store P^T swizzled into KPs: logical (row = col tx*4+jj, col = ty*4+ii)
#pragma unroll
        for (int jj = 0; jj < 4; jj++) {
            int prow = tx * 4 + jj;
            int pcol = (ty ^ tx) << 2;
#pragma unroll
            for (int ii = 0; ii < 4; ii++)
                KPs[prow][pcol + ii] = p[ii][jj];
        }
        __syncthreads();

        // O += P @ V
#pragma unroll 8
        for (int j = 0; j < 64; j++) {
            float4 pv = *(const float4*)&KPs[j][(ty ^ (j >> 2)) << 2];
            float4 vv = *(const float4*)&Vs[j][tx * 4];
            float pa[4] = {pv.x, pv.y, pv.z, pv.w};
            float va[4] = {vv.x, vv.y, vv.z, vv.w};
#pragma unroll
            for (int i = 0; i < 4; i++)
#pragma unroll
                for (int jd = 0; jd < 4; jd++)
                    acc[i][jd] = fmaf(pa[i], va[jd], acc[i][jd]);
        }
    }

    // Normalize and write O in [b, n, h*d] layout (ready for out-proj GEMM)
    float* ob = O + (b * SEQ + qt * 64) * INNER + h * DHEAD;
#pragma unroll
    for (int i = 0; i < 4; i++) {
        float inv = 1.f / l[i];
        int row = ty * 4 + i;
        float4 r;
        r.x = acc[i][0] * inv; r.y = acc[i][1] * inv;
        r.z = acc[i][2] * inv; r.w = acc[i][3] * inv;
        *(float4*)(ob + row * INNER + tx * 4) = r;
    }
}

// ---------------------------------------------------------------------------
extern "C" void kernel_launch(void* const* d_in, const int* in_sizes, int n_in,
                              void* d_out, int out_size)
{
    const float* x   = (const float*)d_in[0];
    const float* Wq  = (const float*)d_in[1];
    const float* Wkv = (const float*)d_in[2];
    const float* Wo  = (const float*)d_in[3];
    const float* bo  = (const float*)d_in[4];
    float* out = (float*)d_out;

    float *q, *k, *v, *o;
    cudaGetSymbolAddress((void**)&q, g_q);
    cudaGetSymbolAddress((void**)&k, g_k);
    cudaGetSymbolAddress((void**)&v, g_v);
    cudaGetSymbolAddress((void**)&o, g_o);

    dim3 blk(256);

    // q = x @ Wq                          [8192,1024] x [1024,1024]
    gemm_kernel<<<dim3(INNER / GBN, TOKENS / GBM), blk>>>(
        x, Wq, q, nullptr, INNER, nullptr, INNER, DIM);

    // [k | v] = x @ Wkv                   [8192,1024] x [1024,2048], split epilogue
    gemm_kernel<<<dim3(2 * INNER / GBN, TOKENS / GBM), blk>>>(
        x, Wkv, k, v, INNER, nullptr, 2 * INNER, DIM);

    // o = softmax(q k^T * scale) v        per (batch, head)
    flash_kernel<<<dim3(SEQ / 64, BATCH * HEADS), blk>>>(q, k, v, o);

    // out = o @ Wo + bo                   [8192,1024] x [1024,1024]
    gemm_kernel<<<dim3(DIM / GBN, TOKENS / GBM), blk>>>(
        o, Wo, out, nullptr, DIM, bo, DIM, DIM);
}

// round 4
// speedup vs baseline: 1.4196x; 1.4196x over previous
#include <cuda_runtime.h>
#include <cuda_bf16.h>
#include <cstdint>

#define BATCH 4
#define SEQ 2048
#define DIM 1024
#define HEADS 16
#define DHEAD 64
#define INNER 1024
#define TOKENS (BATCH * SEQ)
#define ATT_SCALE 0.125f

// ---------------------------------------------------------------------------
// Scratch (allocation-free device globals)
// ---------------------------------------------------------------------------
__device__ float g_q[TOKENS * INNER];
__device__ float g_k[TOKENS * INNER];
__device__ float g_v[TOKENS * INNER];
__device__ __nv_bfloat16 g_xh[TOKENS * DIM];
__device__ __nv_bfloat16 g_xl[TOKENS * DIM];
__device__ __nv_bfloat16 g_oh[TOKENS * INNER];
__device__ __nv_bfloat16 g_ol[TOKENS * INNER];
__device__ __nv_bfloat16 g_wqth[INNER * DIM];
__device__ __nv_bfloat16 g_wqtl[INNER * DIM];
__device__ __nv_bfloat16 g_wkvth[2 * INNER * DIM];
__device__ __nv_bfloat16 g_wkvtl[2 * INNER * DIM];
__device__ __nv_bfloat16 g_woth[DIM * INNER];
__device__ __nv_bfloat16 g_wotl[DIM * INNER];

// ---------------------------------------------------------------------------
// Helpers (base-target PTX only: ldmatrix / mma.sync / cp.async)
// ---------------------------------------------------------------------------
__device__ __forceinline__ uint32_t smem_u32(const void* p) {
    uint32_t a;
    asm("{ .reg .u64 t; cvta.to.shared.u64 t, %1; cvt.u32.u64 %0, t; }"
        : "=r"(a) : "l"(p));
    return a;
}

__device__ __forceinline__ void ldm_x4(uint32_t* r, uint32_t addr) {
    asm volatile("ldmatrix.sync.aligned.m8n8.x4.shared.b16 {%0,%1,%2,%3}, [%4];"
                 : "=r"(r[0]), "=r"(r[1]), "=r"(r[2]), "=r"(r[3]) : "r"(addr));
}

__device__ __forceinline__ void mma16816(float* c, const uint32_t* a, const uint32_t* b) {
    asm volatile(
        "mma.sync.aligned.m16n8k16.row.col.f32.bf16.bf16.f32 "
        "{%0,%1,%2,%3}, {%4,%5,%6,%7}, {%8,%9}, {%0,%1,%2,%3};"
        : "+f"(c[0]), "+f"(c[1]), "+f"(c[2]), "+f"(c[3])
        : "r"(a[0]), "r"(a[1]), "r"(a[2]), "r"(a[3]), "r"(b[0]), "r"(b[1]));
}

__device__ __forceinline__ void cp_async16(uint32_t saddr, const void* gaddr) {
    asm volatile("cp.async.cg.shared.global [%0], [%1], 16;"
                 :: "r"(saddr), "l"(gaddr) : "memory");
}
__device__ __forceinline__ void cp_commit() {
    asm volatile("cp.async.commit_group;" ::: "memory");
}
template <int N>
__device__ __forceinline__ void cp_wait() {
    asm volatile("cp.async.wait_group %0;" :: "n"(N) : "memory");
}

__device__ __forceinline__ void bf16_split(float a, __nv_bfloat16& h, __nv_bfloat16& l) {
    h = __float2bfloat16_rn(a);
    l = __float2bfloat16_rn(a - __bfloat162float(h));
}

// ---------------------------------------------------------------------------
// Prep: split x into bf16 hi/lo
// ---------------------------------------------------------------------------
__global__ void split_x_kernel(const float* __restrict__ in,
                               __nv_bfloat16* __restrict__ oh,
                               __nv_bfloat16* __restrict__ ol) {
    int i = (blockIdx.x * blockDim.x + threadIdx.x) * 4;
    float4 v = *(const float4*)(in + i);
    __nv_bfloat16 h0, h1, h2, h3, l0, l1, l2, l3;
    bf16_split(v.x, h0, l0); bf16_split(v.y, h1, l1);
    bf16_split(v.z, h2, l2); bf16_split(v.w, h3, l3);
    *(__nv_bfloat162*)(oh + i)     = __nv_bfloat162(h0, h1);
    *(__nv_bfloat162*)(oh + i + 2) = __nv_bfloat162(h2, h3);
    *(__nv_bfloat162*)(ol + i)     = __nv_bfloat162(l0, l1);
    *(__nv_bfloat162*)(ol + i + 2) = __nv_bfloat162(l2, l3);
}

// ---------------------------------------------------------------------------
// Prep: transpose W[K,N] -> WT[N,K] split into bf16 hi/lo
// ---------------------------------------------------------------------------
__global__ void transpose_split_kernel(const float* __restrict__ W,
                                       __nv_bfloat16* __restrict__ WTh,
                                       __nv_bfloat16* __restrict__ WTl,
                                       int K, int N) {
    __shared__ float t[32][33];
    int k0 = blockIdx.x * 32, n0 = blockIdx.y * 32;
    int x = threadIdx.x, y = threadIdx.y;
#pragma unroll
    for (int j = 0; j < 32; j += 8)
        t[y + j][x] = W[(size_t)(k0 + y + j) * N + n0 + x];
    __syncthreads();
#pragma unroll
    for (int j = 0; j < 32; j += 8) {
        float a = t[x][y + j];
        __nv_bfloat16 h, l;
        bf16_split(a, h, l);
        size_t o = (size_t)(n0 + y + j) * K + k0 + x;
        WTh[o] = h; WTl[o] = l;
    }
}

// ---------------------------------------------------------------------------
// HMMA bf16x3 GEMM:  C[M,N] = A[M,K] @ BT[N,K]^T  (fp32 accumulate)
// CTA tile 128x128, k-block 32. 8 warps = 2(M) x 4(N); warp tile 64x32.
// Smem per stage: Ah/Al/BTh/BTl, each [128 rows][32 bf16] = 8KB, XOR-swizzled
// 16B chunks (chunk ^= (row>>1)&3) -> conflict-free ldmatrix. 2 stages = 64KB.
// Columns < splitN -> C0 (ld=splitN), else C1.
// ---------------------------------------------------------------------------
#define HT_TK 32
#define HT_TILE 8192                   // bytes per [128][32] bf16 tile
#define HT_STAGE (4 * HT_TILE)         // 32 KB
#define HT_SMEM (2 * HT_STAGE)         // 64 KB

// byte offset of 16B chunk (row, chunk) inside one tile
#define HSWZ(row, chunk) (((row) << 6) + (((chunk) ^ (((row) >> 1) & 3)) << 4))

__global__ __launch_bounds__(256)
void gemm_tc(const __nv_bfloat16* __restrict__ Ah,
             const __nv_bfloat16* __restrict__ Al,
             const __nv_bfloat16* __restrict__ Bh,
             const __nv_bfloat16* __restrict__ Bl,
             float* __restrict__ C0, float* __restrict__ C1, int splitN,
             const float* __restrict__ bias, int N, int K)
{
    extern __shared__ char smem[];
    const uint32_t sb = smem_u32(smem);
    const int tid = threadIdx.x;
    const int wid = tid >> 5;
    const int lane = tid & 31;
    const int m0 = blockIdx.y * 128;
    const int n0 = blockIdx.x * 128;
    const int nkb = K / HT_TK;

    const int wm = (wid & 1) * 64;   // warp M offset in tile
    const int wn = (wid >> 1) * 32;  // warp N offset in tile

    // loader mapping: each thread copies 2 16B chunks per tile
    // tile has 128 rows x 4 chunks = 512 chunks
    const int lrow0 = tid >> 1;               // chunks 0..1 or 2..3 of row tid>>1
    const int lch0  = (tid & 1) * 2;

    auto load_stage = [&](int st, int kb) {
        const uint32_t stg = sb + st * HT_STAGE;
        const int kc = kb * HT_TK;  // starting k element
        const __nv_bfloat16* srcs[4] = {Ah, Al, Bh, Bl};
        const int rows0[4] = {m0, m0, n0, n0};
#pragma unroll
        for (int t = 0; t < 4; t++) {
            const __nv_bfloat16* s = srcs[t] + (size_t)(rows0[t] + lrow0) * K + kc;
#pragma unroll
            for (int c = 0; c < 2; c++) {
                cp_async16(stg + t * HT_TILE + HSWZ(lrow0, lch0 + c),
                           s + (lch0 + c) * 8);
            }
        }
    };

    float acc[4][4][4];
#pragma unroll
    for (int i = 0; i < 4; i++)
#pragma unroll
        for (int j = 0; j < 4; j++)
#pragma unroll
            for (int e = 0; e < 4; e++) acc[i][j][e] = 0.f;

    // ldmatrix lane address components
    const int a_row = lane & 15;            // rows 0..15 of m-tile
    const int a_chk = lane >> 4;            // 0/1 -> k chunk within k16
    const int b_row = (lane & 7) + ((lane >> 4) << 3);  // n row within n16 group
    const int b_chk = (lane >> 3) & 1;

    load_stage(0, 0);
    cp_commit();

    for (int kb = 0; kb < nkb; kb++) {
        if (kb + 1 < nkb) {
            load_stage((kb + 1) & 1, kb + 1);
            cp_commit();
            cp_wait<1>();
        } else {
            cp_wait<0>();
        }
        __syncthreads();

        const uint32_t stg = sb + (kb & 1) * HT_STAGE;
        const uint32_t sAh = stg;
        const uint32_t sAl = stg + HT_TILE;
        const uint32_t sBh = stg + 2 * HT_TILE;
        const uint32_t sBl = stg + 3 * HT_TILE;

#pragma unroll
        for (int kk = 0; kk < 2; kk++) {
            uint32_t ah[4][4], al[4][4], bh[2][4], bl[2][4];
#pragma unroll
            for (int mt = 0; mt < 4; mt++) {
                int r = wm + mt * 16 + a_row;
                int c = kk * 2 + a_chk;
                ldm_x4(ah[mt], sAh + HSWZ(r, c));
                ldm_x4(al[mt], sAl + HSWZ(r, c));
            }
#pragma unroll
            for (int ng = 0; ng < 2; ng++) {
                int r = wn + ng * 16 + b_row;
                int c = kk * 2 + b_chk;
                ldm_x4(bh[ng], sBh + HSWZ(r, c));
                ldm_x4(bl[ng], sBl + HSWZ(r, c));
            }
#pragma unroll
            for (int mt = 0; mt < 4; mt++) {
#pragma unroll
                for (int nt = 0; nt < 4; nt++) {
                    const int ng = nt >> 1, hf = (nt & 1) * 2;
                    mma16816(acc[mt][nt], ah[mt], &bh[ng][hf]);
                    mma16816(acc[mt][nt], ah[mt], &bl[ng][hf]);
                    mma16816(acc[mt][nt], al[mt], &bh[ng][hf]);
                }
            }
        }
        __syncthreads();
    }

    // epilogue
    float* Cb; int ldc, c0;
    if (n0 < splitN) { Cb = C0; ldc = splitN;     c0 = n0; }
    else             { Cb = C1; ldc = N - splitN; c0 = n0 - splitN; }

    const int erow = lane >> 2;
    const int ecol = (lane & 3) * 2;
#pragma unroll
    for (int mt = 0; mt < 4; mt++) {
#pragma unroll
        for (int nt = 0; nt < 4; nt++) {
            int gcol = n0 + wn + nt * 8 + ecol;
            float b0 = 0.f, b1 = 0.f;
            if (bias) { b0 = bias[gcol]; b1 = bias[gcol + 1]; }
            int r0 = m0 + wm + mt * 16 + erow;
            float2 v0 = make_float2(acc[mt][nt][0] + b0, acc[mt][nt][1] + b1);
            float2 v1 = make_float2(acc[mt][nt][2] + b0, acc[mt][nt][3] + b1);
            int lcol = c0 + wn + nt * 8 + ecol;
            *(float2*)(Cb + (size_t)r0 * ldc + lcol)       = v0;
            *(float2*)(Cb + (size_t)(r0 + 8) * ldc + lcol) = v1;
        }
    }
}

// ---------------------------------------------------------------------------
// Flash attention, fp32 SIMT (unchanged math). Output written as bf16 hi/lo.
// ---------------------------------------------------------------------------
__global__ __launch_bounds__(256, 2)
void flash_kernel(const float* __restrict__ Q, const float* __restrict__ Kg,
                  const float* __restrict__ Vg,
                  __nv_bfloat16* __restrict__ Oh, __nv_bfloat16* __restrict__ Ol)
{
    __shared__ float Qs[64][64];
    __shared__ float KPs[64][64];
    __shared__ float Vs[64][64];

    const int bh  = blockIdx.y;
    const int b   = bh >> 4;
    const int h   = bh & 15;
    const int qt  = blockIdx.x;
    const int tid = threadIdx.x;
    const int ty  = tid >> 4;
    const int tx  = tid & 15;

    const float* qb = Q  + (size_t)(b * SEQ + qt * 64) * INNER + h * DHEAD;
    const float* kb = Kg + (size_t)b * SEQ * INNER + h * DHEAD;
    const float* vb = Vg + (size_t)b * SEQ * INNER + h * DHEAD;

#pragma unroll
    for (int rep = 0; rep < 4; rep++) {
        int f   = tid + rep * 256;
        int row = f >> 4;
        int d4  = f & 15;
        float4 v = *(const float4*)(qb + (size_t)row * INNER + d4 * 4);
        int pc = (((row >> 2) ^ d4) << 2) + (row & 3);
        Qs[d4 * 4 + 0][pc] = v.x;
        Qs[d4 * 4 + 1][pc] = v.y;
        Qs[d4 * 4 + 2][pc] = v.z;
        Qs[d4 * 4 + 3][pc] = v.w;
    }

    float acc[4][4];
    float m[4], l[4];
#pragma unroll
    for (int i = 0; i < 4; i++) {
        m[i] = -1e30f; l[i] = 0.f;
#pragma unroll
        for (int j = 0; j < 4; j++) acc[i][j] = 0.f;
    }

    for (int kb0 = 0; kb0 < SEQ / 64; kb0++) {
        __syncthreads();
        const float* kp = kb + (size_t)kb0 * 64 * INNER;
        const float* vp = vb + (size_t)kb0 * 64 * INNER;
#pragma unroll
        for (int rep = 0; rep < 4; rep++) {
            int f   = tid + rep * 256;
            int row = f >> 4;
            int d4  = f & 15;
            float4 kv = *(const float4*)(kp + (size_t)row * INNER + d4 * 4);
            int pc = (((row >> 2) ^ d4) << 2) + (row & 3);
            KPs[d4 * 4 + 0][pc] = kv.x;
            KPs[d4 * 4 + 1][pc] = kv.y;
            KPs[d4 * 4 + 2][pc] = kv.z;
            KPs[d4 * 4 + 3][pc] = kv.w;
            float4 vv = *(const float4*)(vp + (size_t)row * INNER + d4 * 4);
            *(float4*)&Vs[row][d4 * 4] = vv;
        }
        __syncthreads();

        float s[4][4];
#pragma unroll
        for (int i = 0; i < 4; i++)
#pragma unroll
            for (int j = 0; j < 4; j++) s[i][j] = 0.f;
#pragma unroll 8
        for (int kd = 0; kd < 64; kd++) {
            float4 a = *(const float4*)&Qs[kd][(ty ^ (kd >> 2)) << 2];
            float4 c = *(const float4*)&KPs[kd][(tx ^ (kd >> 2)) << 2];
            float av[4] = {a.x, a.y, a.z, a.w};
            float cv[4] = {c.x, c.y, c.z, c.w};
#pragma unroll
            for (int i = 0; i < 4; i++)
#pragma unroll
                for (int j = 0; j < 4; j++)
                    s[i][j] = fmaf(av[i], cv[j], s[i][j]);
        }

        float p[4][4];
#pragma unroll
        for (int i = 0; i < 4; i++) {
            float rm = -1e30f;
#pragma unroll
            for (int j = 0; j < 4; j++) {
                s[i][j] *= ATT_SCALE;
                rm = fmaxf(rm, s[i][j]);
            }
            rm = fmaxf(rm, __shfl_xor_sync(0xffffffffu, rm, 8));
            rm = fmaxf(rm, __shfl_xor_sync(0xffffffffu, rm, 4));
            rm = fmaxf(rm, __shfl_xor_sync(0xffffffffu, rm, 2));
            rm = fmaxf(rm, __shfl_xor_sync(0xffffffffu, rm, 1));
            float mn    = fmaxf(m[i], rm);
            float alpha = __expf(m[i] - mn);
            m[i] = mn;
            float rs = 0.f;
#pragma unroll
            for (int j = 0; j < 4; j++) {
                p[i][j] = __expf(s[i][j] - mn);
                rs += p[i][j];
            }
            rs += __shfl_xor_sync(0xffffffffu, rs, 8);
            rs += __shfl_xor_sync(0xffffffffu, rs, 4);
            rs += __shfl_xor_sync(0xffffffffu, rs, 2);
            rs += __shfl_xor_sync(0xffffffffu, rs, 1);
            l[i] = l[i] * alpha + rs;
#pragma unroll
            for (int j = 0; j < 4; j++) acc[i][j] *= alpha;
        }

        __syncthreads();
#pragma unroll
        for (int jj = 0; jj < 4; jj++) {
            int prow = tx * 4 + jj;
            int pcol = (ty ^ tx) << 2;
#pragma unroll
            for (int ii = 0; ii < 4; ii++)
                KPs[prow][pcol + ii] = p[ii][jj];
        }
        __syncthreads();

#pragma unroll 8
        for (int j = 0; j < 64; j++) {
            float4 pv = *(const float4*)&KPs[j][(ty ^ (j >> 2)) << 2];
            float4 vv = *(const float4*)&Vs[j][tx * 4];
            float pa[4] = {pv.x, pv.y, pv.z, pv.w};
            float va[4] = {vv.x, vv.y, vv.z, vv.w};
#pragma unroll
            for (int i = 0; i < 4; i++)
#pragma unroll
                for (int jd = 0; jd < 4; jd++)
                    acc[i][jd] = fmaf(pa[i], va[jd], acc[i][jd]);
        }
    }

    size_t obase = (size_t)(b * SEQ + qt * 64) * INNER + h * DHEAD;
#pragma unroll
    for (int i = 0; i < 4; i++) {
        float inv = 1.f / l[i];
        int row = ty * 4 + i;
        size_t o = obase + (size_t)row * INNER + tx * 4;
        __nv_bfloat16 h0, h1, h2, h3, l0, l1, l2, l3;
        bf16_split(acc[i][0] * inv, h0, l0);
        bf16_split(acc[i][1] * inv, h1, l1);
        bf16_split(acc[i][2] * inv, h2, l2);
        bf16_split(acc[i][3] * inv, h3, l3);
        *(__nv_bfloat162*)(Oh + o)     = __nv_bfloat162(h0, h1);
        *(__nv_bfloat162*)(Oh + o + 2) = __nv_bfloat162(h2, h3);
        *(__nv_bfloat162*)(Ol + o)     = __nv_bfloat162(l0, l1);
        *(__nv_bfloat162*)(Ol + o + 2) = __nv_bfloat162(l2, l3);
    }
}

// ---------------------------------------------------------------------------
extern "C" void kernel_launch(void* const* d_in, const int* in_sizes, int n_in,
                              void* d_out, int out_size)
{
    const float* x   = (const float*)d_in[0];
    const float* Wq  = (const float*)d_in[1];
    const float* Wkv = (const float*)d_in[2];
    const float* Wo  = (const float*)d_in[3];
    const float* bo  = (const float*)d_in[4];
    float* out = (float*)d_out;

    float *q, *k, *v;
    __nv_bfloat16 *xh, *xl, *oh, *ol, *wqth, *wqtl, *wkvth, *wkvtl, *woth, *wotl;
    cudaGetSymbolAddress((void**)&q, g_q);
    cudaGetSymbolAddress((void**)&k, g_k);
    cudaGetSymbolAddress((void**)&v, g_v);
    cudaGetSymbolAddress((void**)&xh, g_xh);
    cudaGetSymbolAddress((void**)&xl, g_xl);
    cudaGetSymbolAddress((void**)&oh, g_oh);
    cudaGetSymbolAddress((void**)&ol, g_ol);
    cudaGetSymbolAddress((void**)&wqth, g_wqth);
    cudaGetSymbolAddress((void**)&wqtl, g_wqtl);
    cudaGetSymbolAddress((void**)&wkvth, g_wkvth);
    cudaGetSymbolAddress((void**)&wkvtl, g_wkvtl);
    cudaGetSymbolAddress((void**)&woth, g_woth);
    cudaGetSymbolAddress((void**)&wotl, g_wotl);

    cudaFuncSetAttribute(gemm_tc, cudaFuncAttributeMaxDynamicSharedMemorySize, HT_SMEM);

    // prep: split x, transpose+split weights
    split_x_kernel<<<TOKENS * DIM / (256 * 4), 256>>>(x, xh, xl);
    transpose_split_kernel<<<dim3(DIM / 32, INNER / 32), dim3(32, 8)>>>(Wq, wqth, wqtl, DIM, INNER);
    transpose_split_kernel<<<dim3(DIM / 32, 2 * INNER / 32), dim3(32, 8)>>>(Wkv, wkvth, wkvtl, DIM, 2 * INNER);
    transpose_split_kernel<<<dim3(INNER / 32, DIM / 32), dim3(32, 8)>>>(Wo, woth, wotl, INNER, DIM);

    // q = x @ Wq
    gemm_tc<<<dim3(INNER / 128, TOKENS / 128), 256, HT_SMEM>>>(
        xh, xl, wqth, wqtl, q, nullptr, INNER, nullptr, INNER, DIM);
    // [k | v] = x @ Wkv
    gemm_tc<<<dim3(2 * INNER / 128, TOKENS / 128), 256, HT_SMEM>>>(
        xh, xl, wkvth, wkvtl, k, v, INNER, nullptr, 2 * INNER, DIM);
    // attention (fp32), emits bf16-split O
    flash_kernel<<<dim3(SEQ / 64, BATCH * HEADS), 256>>>(q, k, v, oh, ol);
    // out = O @ Wo + bo
    gemm_tc<<<dim3(DIM / 128, TOKENS / 128), 256, HT_SMEM>>>(
        oh, ol, woth, wotl, out, nullptr, DIM, bo, DIM, INNER);
}

// round 5
// speedup vs baseline: 3.0618x; 2.1569x over previous
#include <cuda_runtime.h>
#include <cuda_bf16.h>
#include <cstdint>

#define BATCH 4
#define SEQ 2048
#define DIM 1024
#define HEADS 16
#define DHEAD 64
#define INNER 1024
#define TOKENS (BATCH * SEQ)
#define ATT_SCALE 0.125f

// ---------------------------------------------------------------------------
// Scratch (allocation-free device globals)
// ---------------------------------------------------------------------------
__device__ __nv_bfloat16 g_xh[TOKENS * DIM];
__device__ __nv_bfloat16 g_xl[TOKENS * DIM];
__device__ __nv_bfloat16 g_qh[TOKENS * INNER];
__device__ __nv_bfloat16 g_ql[TOKENS * INNER];
__device__ __nv_bfloat16 g_kh[TOKENS * INNER];
__device__ __nv_bfloat16 g_kl[TOKENS * INNER];
__device__ __nv_bfloat16 g_vh[TOKENS * INNER];
__device__ __nv_bfloat16 g_vl[TOKENS * INNER];
__device__ __nv_bfloat16 g_oh[TOKENS * INNER];
__device__ __nv_bfloat16 g_ol[TOKENS * INNER];
__device__ __nv_bfloat16 g_wqth[INNER * DIM];
__device__ __nv_bfloat16 g_wqtl[INNER * DIM];
__device__ __nv_bfloat16 g_wkvth[2 * INNER * DIM];
__device__ __nv_bfloat16 g_wkvtl[2 * INNER * DIM];
__device__ __nv_bfloat16 g_woth[DIM * INNER];
__device__ __nv_bfloat16 g_wotl[DIM * INNER];

// ---------------------------------------------------------------------------
// Helpers (base-target PTX only: ldmatrix / mma.sync / cp.async)
// ---------------------------------------------------------------------------
__device__ __forceinline__ uint32_t smem_u32(const void* p) {
    uint32_t a;
    asm("{ .reg .u64 t; cvta.to.shared.u64 t, %1; cvt.u32.u64 %0, t; }"
        : "=r"(a) : "l"(p));
    return a;
}

__device__ __forceinline__ void ldm_x4(uint32_t* r, uint32_t addr) {
    asm volatile("ldmatrix.sync.aligned.m8n8.x4.shared.b16 {%0,%1,%2,%3}, [%4];"
                 : "=r"(r[0]), "=r"(r[1]), "=r"(r[2]), "=r"(r[3]) : "r"(addr));
}

__device__ __forceinline__ void ldm_x4_t(uint32_t* r, uint32_t addr) {
    asm volatile("ldmatrix.sync.aligned.m8n8.x4.trans.shared.b16 {%0,%1,%2,%3}, [%4];"
                 : "=r"(r[0]), "=r"(r[1]), "=r"(r[2]), "=r"(r[3]) : "r"(addr));
}

__device__ __forceinline__ void mma16816(float* c, const uint32_t* a, const uint32_t* b) {
    asm volatile(
        "mma.sync.aligned.m16n8k16.row.col.f32.bf16.bf16.f32 "
        "{%0,%1,%2,%3}, {%4,%5,%6,%7}, {%8,%9}, {%0,%1,%2,%3};"
        : "+f"(c[0]), "+f"(c[1]), "+f"(c[2]), "+f"(c[3])
        : "r"(a[0]), "r"(a[1]), "r"(a[2]), "r"(a[3]), "r"(b[0]), "r"(b[1]));
}

__device__ __forceinline__ void cp_async16(uint32_t saddr, const void* gaddr) {
    asm volatile("cp.async.cg.shared.global [%0], [%1], 16;"
                 :: "r"(saddr), "l"(gaddr) : "memory");
}
__device__ __forceinline__ void cp_commit() {
    asm volatile("cp.async.commit_group;" ::: "memory");
}
template <int N>
__device__ __forceinline__ void cp_wait() {
    asm volatile("cp.async.wait_group %0;" :: "n"(N) : "memory");
}

__device__ __forceinline__ void bf16_split(float a, __nv_bfloat16& h, __nv_bfloat16& l) {
    h = __float2bfloat16_rn(a);
    l = __float2bfloat16_rn(a - __bfloat162float(h));
}

__device__ __forceinline__ void pack_split(float x, float y, uint32_t& hi, uint32_t& lo) {
    __nv_bfloat16 hx = __float2bfloat16_rn(x);
    __nv_bfloat16 hy = __float2bfloat16_rn(y);
    __nv_bfloat162 H(hx, hy);
    __nv_bfloat162 L(__float2bfloat16_rn(x - __bfloat162float(hx)),
                     __float2bfloat16_rn(y - __bfloat162float(hy)));
    hi = *(uint32_t*)&H;
    lo = *(uint32_t*)&L;
}

// ---------------------------------------------------------------------------
// Prep: split x into bf16 hi/lo
// ---------------------------------------------------------------------------
__global__ void split_x_kernel(const float* __restrict__ in,
                               __nv_bfloat16* __restrict__ oh,
                               __nv_bfloat16* __restrict__ ol) {
    int i = (blockIdx.x * blockDim.x + threadIdx.x) * 4;
    float4 v = *(const float4*)(in + i);
    __nv_bfloat16 h0, h1, h2, h3, l0, l1, l2, l3;
    bf16_split(v.x, h0, l0); bf16_split(v.y, h1, l1);
    bf16_split(v.z, h2, l2); bf16_split(v.w, h3, l3);
    *(__nv_bfloat162*)(oh + i)     = __nv_bfloat162(h0, h1);
    *(__nv_bfloat162*)(oh + i + 2) = __nv_bfloat162(h2, h3);
    *(__nv_bfloat162*)(ol + i)     = __nv_bfloat162(l0, l1);
    *(__nv_bfloat162*)(ol + i + 2) = __nv_bfloat162(l2, l3);
}

// ---------------------------------------------------------------------------
// Prep: transpose W[K,N] -> WT[N,K] split into bf16 hi/lo
// ---------------------------------------------------------------------------
__global__ void transpose_split_kernel(const float* __restrict__ W,
                                       __nv_bfloat16* __restrict__ WTh,
                                       __nv_bfloat16* __restrict__ WTl,
                                       int K, int N) {
    __shared__ float t[32][33];
    int k0 = blockIdx.x * 32, n0 = blockIdx.y * 32;
    int x = threadIdx.x, y = threadIdx.y;
#pragma unroll
    for (int j = 0; j < 32; j += 8)
        t[y + j][x] = W[(size_t)(k0 + y + j) * N + n0 + x];
    __syncthreads();
#pragma unroll
    for (int j = 0; j < 32; j += 8) {
        float a = t[x][y + j];
        __nv_bfloat16 h, l;
        bf16_split(a, h, l);
        size_t o = (size_t)(n0 + y + j) * K + k0 + x;
        WTh[o] = h; WTl[o] = l;
    }
}

// ---------------------------------------------------------------------------
// HMMA bf16x3 GEMM:  C[M,N] = A[M,K] @ BT[N,K]^T  (fp32 accumulate)
// CTA tile 128x128, k-block 32, 8 warps = 2(M) x 4(N), warp tile 64x32.
// Output: fp32 (C0/C1) OR bf16 hi/lo split scaled by oscale (C0h.. non-null).
// ---------------------------------------------------------------------------
#define HT_TK 32
#define HT_TILE 8192
#define HT_STAGE (4 * HT_TILE)
#define HT_SMEM (2 * HT_STAGE)
#define HSWZ(row, chunk) (((row) << 6) + (((chunk) ^ (((row) >> 1) & 3)) << 4))

__global__ __launch_bounds__(256)
void gemm_tc(const __nv_bfloat16* __restrict__ Ah,
             const __nv_bfloat16* __restrict__ Al,
             const __nv_bfloat16* __restrict__ Bh,
             const __nv_bfloat16* __restrict__ Bl,
             float* __restrict__ C0, float* __restrict__ C1,
             __nv_bfloat16* __restrict__ C0h, __nv_bfloat16* __restrict__ C0l,
             __nv_bfloat16* __restrict__ C1h, __nv_bfloat16* __restrict__ C1l,
             int splitN, const float* __restrict__ bias, float oscale,
             int N, int K)
{
    extern __shared__ char smem[];
    const uint32_t sb = smem_u32(smem);
    const int tid = threadIdx.x;
    const int wid = tid >> 5;
    const int lane = tid & 31;
    const int m0 = blockIdx.y * 128;
    const int n0 = blockIdx.x * 128;
    const int nkb = K / HT_TK;

    const int wm = (wid & 1) * 64;
    const int wn = (wid >> 1) * 32;

    const int lrow0 = tid >> 1;
    const int lch0  = (tid & 1) * 2;

    auto load_stage = [&](int st, int kb) {
        const uint32_t stg = sb + st * HT_STAGE;
        const int kc = kb * HT_TK;
        const __nv_bfloat16* srcs[4] = {Ah, Al, Bh, Bl};
        const int rows0[4] = {m0, m0, n0, n0};
#pragma unroll
        for (int t = 0; t < 4; t++) {
            const __nv_bfloat16* s = srcs[t] + (size_t)(rows0[t] + lrow0) * K + kc;
#pragma unroll
            for (int c = 0; c < 2; c++) {
                cp_async16(stg + t * HT_TILE + HSWZ(lrow0, lch0 + c),
                           s + (lch0 + c) * 8);
            }
        }
    };

    float acc[4][4][4];
#pragma unroll
    for (int i = 0; i < 4; i++)
#pragma unroll
        for (int j = 0; j < 4; j++)
#pragma unroll
            for (int e = 0; e < 4; e++) acc[i][j][e] = 0.f;

    const int a_row = lane & 15;
    const int a_chk = lane >> 4;
    const int b_row = (lane & 7) + ((lane >> 4) << 3);
    const int b_chk = (lane >> 3) & 1;

    load_stage(0, 0);
    cp_commit();

    for (int kb = 0; kb < nkb; kb++) {
        if (kb + 1 < nkb) {
            load_stage((kb + 1) & 1, kb + 1);
            cp_commit();
            cp_wait<1>();
        } else {
            cp_wait<0>();
        }
        __syncthreads();

        const uint32_t stg = sb + (kb & 1) * HT_STAGE;
        const uint32_t sAh = stg;
        const uint32_t sAl = stg + HT_TILE;
        const uint32_t sBh = stg + 2 * HT_TILE;
        const uint32_t sBl = stg + 3 * HT_TILE;

#pragma unroll
        for (int kk = 0; kk < 2; kk++) {
            uint32_t ah[4][4], al[4][4], bh[2][4], bl[2][4];
#pragma unroll
            for (int mt = 0; mt < 4; mt++) {
                int r = wm + mt * 16 + a_row;
                int c = kk * 2 + a_chk;
                ldm_x4(ah[mt], sAh + HSWZ(r, c));
                ldm_x4(al[mt], sAl + HSWZ(r, c));
            }
#pragma unroll
            for (int ng = 0; ng < 2; ng++) {
                int r = wn + ng * 16 + b_row;
                int c = kk * 2 + b_chk;
                ldm_x4(bh[ng], sBh + HSWZ(r, c));
                ldm_x4(bl[ng], sBl + HSWZ(r, c));
            }
#pragma unroll
            for (int mt = 0; mt < 4; mt++) {
#pragma unroll
                for (int nt = 0; nt < 4; nt++) {
                    const int ng = nt >> 1, hf = (nt & 1) * 2;
                    mma16816(acc[mt][nt], ah[mt], &bh[ng][hf]);
                    mma16816(acc[mt][nt], ah[mt], &bl[ng][hf]);
                    mma16816(acc[mt][nt], al[mt], &bh[ng][hf]);
                }
            }
        }
        __syncthreads();
    }

    const int erow = lane >> 2;
    const int ecol = (lane & 3) * 2;

    if (C0h) {
        // split bf16 output (scaled by oscale)
        __nv_bfloat16 *Oh, *Ol; int ldc, c0;
        if (n0 < splitN) { Oh = C0h; Ol = C0l; ldc = splitN;     c0 = n0; }
        else             { Oh = C1h; Ol = C1l; ldc = N - splitN; c0 = n0 - splitN; }
#pragma unroll
        for (int mt = 0; mt < 4; mt++) {
#pragma unroll
            for (int nt = 0; nt < 4; nt++) {
                int r0 = m0 + wm + mt * 16 + erow;
                int lcol = c0 + wn + nt * 8 + ecol;
                uint32_t h0, l0h, h1, l1h;
                pack_split(acc[mt][nt][0] * oscale, acc[mt][nt][1] * oscale, h0, l0h);
                pack_split(acc[mt][nt][2] * oscale, acc[mt][nt][3] * oscale, h1, l1h);
                *(uint32_t*)(Oh + (size_t)r0 * ldc + lcol)       = h0;
                *(uint32_t*)(Ol + (size_t)r0 * ldc + lcol)       = l0h;
                *(uint32_t*)(Oh + (size_t)(r0 + 8) * ldc + lcol) = h1;
                *(uint32_t*)(Ol + (size_t)(r0 + 8) * ldc + lcol) = l1h;
            }
        }
    } else {
        float* Cb; int ldc, c0;
        if (n0 < splitN) { Cb = C0; ldc = splitN;     c0 = n0; }
        else             { Cb = C1; ldc = N - splitN; c0 = n0 - splitN; }
#pragma unroll
        for (int mt = 0; mt < 4; mt++) {
#pragma unroll
            for (int nt = 0; nt < 4; nt++) {
                int gcol = n0 + wn + nt * 8 + ecol;
                float b0 = 0.f, b1 = 0.f;
                if (bias) { b0 = bias[gcol]; b1 = bias[gcol + 1]; }
                int r0 = m0 + wm + mt * 16 + erow;
                float2 v0 = make_float2(acc[mt][nt][0] + b0, acc[mt][nt][1] + b1);
                float2 v1 = make_float2(acc[mt][nt][2] + b0, acc[mt][nt][3] + b1);
                int lcol = c0 + wn + nt * 8 + ecol;
                *(float2*)(Cb + (size_t)r0 * ldc + lcol)       = v0;
                *(float2*)(Cb + (size_t)(r0 + 8) * ldc + lcol) = v1;
            }
        }
    }
}

// ---------------------------------------------------------------------------
// Flash attention on mma.sync, bf16x3 split for S and P·V.
// CTA = 128 q rows x one (b,h). 8 warps, 16 rows each. K-chunks of 64,
// double-buffered cp.async. Q pre-scaled by ATT_SCALE at projection.
// smem: Qh/Ql 16KB each; per stage Kh/Kl/Vh/Vl 8KB each -> 96KB total.
// Rows are 64 bf16 = 128B, swizzled (chunk ^= row&7) -> conflict-free ldmatrix.
// ---------------------------------------------------------------------------
#define FA_BQ 128
#define FA_BK 64
#define FA_NC (SEQ / FA_BK)
#define FSWZ(row, chunk) (((row) << 7) + ((((chunk) ^ (row)) & 7) << 4))
#define FA_SMEM (32768 + 2 * 32768)

__global__ __launch_bounds__(256, 1)
void flash_tc(const __nv_bfloat16* __restrict__ Qh, const __nv_bfloat16* __restrict__ Ql,
              const __nv_bfloat16* __restrict__ Kh, const __nv_bfloat16* __restrict__ Kl,
              const __nv_bfloat16* __restrict__ Vh, const __nv_bfloat16* __restrict__ Vl,
              __nv_bfloat16* __restrict__ Oh, __nv_bfloat16* __restrict__ Ol)
{
    extern __shared__ char smem[];
    const uint32_t sb = smem_u32(smem);
    const int tid = threadIdx.x;
    const int wid = tid >> 5;
    const int lane = tid & 31;
    const int qt = blockIdx.x;
    const int b  = blockIdx.y >> 4;
    const int h  = blockIdx.y & 15;

    const size_t base_q  = (size_t)(b * SEQ + qt * FA_BQ) * INNER + h * DHEAD;
    const size_t base_kv = (size_t)b * SEQ * INNER + h * DHEAD;

    // ---- Q load (group 0, together with KV stage 0) ----
    {
        int row = tid >> 3, chunk = tid & 7;
#pragma unroll
        for (int p = 0; p < 4; p++) {
            int r = row + p * 32;
            size_t go = base_q + (size_t)r * INNER + chunk * 8;
            cp_async16(sb +         FSWZ(r, chunk), Qh + go);
            cp_async16(sb + 16384 + FSWZ(r, chunk), Ql + go);
        }
    }
    auto load_kv = [&](int st, int kc) {
        const uint32_t stg = sb + 32768 + st * 32768;
        int row = tid >> 3, chunk = tid & 7;
        size_t gk = base_kv + (size_t)(kc * FA_BK) * INNER + chunk * 8;
#pragma unroll
        for (int p = 0; p < 2; p++) {
            int r = row + p * 32;
            size_t go = gk + (size_t)r * INNER;
            cp_async16(stg +         FSWZ(r, chunk), Kh + go);
            cp_async16(stg +  8192 + FSWZ(r, chunk), Kl + go);
            cp_async16(stg + 16384 + FSWZ(r, chunk), Vh + go);
            cp_async16(stg + 24576 + FSWZ(r, chunk), Vl + go);
        }
    };
    load_kv(0, 0); cp_commit();
    load_kv(1, 1); cp_commit();

    uint32_t qfh[4][4], qfl[4][4];
    float oacc[8][4];
#pragma unroll
    for (int j = 0; j < 8; j++)
#pragma unroll
        for (int e = 0; e < 4; e++) oacc[j][e] = 0.f;
    float m0 = -1e30f, m1 = -1e30f, l0 = 0.f, l1 = 0.f;

    for (int kc = 0; kc < FA_NC; kc++) {
        if (kc == FA_NC - 1) cp_wait<0>(); else cp_wait<1>();
        __syncthreads();

        if (kc == 0) {
            // Q fragments (A operand, m16k16 per k-step)
#pragma unroll
            for (int kk = 0; kk < 4; kk++) {
                int r = wid * 16 + (lane & 15);
                int c = 2 * kk + (lane >> 4);
                ldm_x4(qfh[kk], sb +         FSWZ(r, c));
                ldm_x4(qfl[kk], sb + 16384 + FSWZ(r, c));
            }
        }
        const uint32_t stg = sb + 32768 + (kc & 1) * 32768;

        // ---- S = Q @ K^T (bf16x3) ----
        float sacc[8][4];
#pragma unroll
        for (int t = 0; t < 8; t++)
#pragma unroll
            for (int e = 0; e < 4; e++) sacc[t][e] = 0.f;
#pragma unroll
        for (int kk = 0; kk < 4; kk++) {
            uint32_t kbh[4][4], kbl[4][4];
#pragma unroll
            for (int G = 0; G < 4; G++) {
                int r = 16 * G + ((lane >> 4) << 3) + (lane & 7);
                int c = 2 * kk + ((lane >> 3) & 1);
                ldm_x4(kbh[G], stg +        FSWZ(r, c));
                ldm_x4(kbl[G], stg + 8192 + FSWZ(r, c));
            }
#pragma unroll
            for (int t = 0; t < 8; t++) {
                const int G = t >> 1, hf = (t & 1) * 2;
                mma16816(sacc[t], qfh[kk], &kbh[G][hf]);
                mma16816(sacc[t], qfh[kk], &kbl[G][hf]);
                mma16816(sacc[t], qfl[kk], &kbh[G][hf]);
            }
        }

        // ---- online softmax (rows r=lane>>2 and r+8; scale folded into Q) ----
        float mx0 = -1e30f, mx1 = -1e30f;
#pragma unroll
        for (int t = 0; t < 8; t++) {
            mx0 = fmaxf(mx0, fmaxf(sacc[t][0], sacc[t][1]));
            mx1 = fmaxf(mx1, fmaxf(sacc[t][2], sacc[t][3]));
        }
        mx0 = fmaxf(mx0, __shfl_xor_sync(0xffffffffu, mx0, 1));
        mx0 = fmaxf(mx0, __shfl_xor_sync(0xffffffffu, mx0, 2));
        mx1 = fmaxf(mx1, __shfl_xor_sync(0xffffffffu, mx1, 1));
        mx1 = fmaxf(mx1, __shfl_xor_sync(0xffffffffu, mx1, 2));
        float mn0 = fmaxf(m0, mx0), mn1 = fmaxf(m1, mx1);
        float a0 = __expf(m0 - mn0), a1 = __expf(m1 - mn1);
        m0 = mn0; m1 = mn1;
        float s0 = 0.f, s1 = 0.f;
#pragma unroll
        for (int t = 0; t < 8; t++) {
            sacc[t][0] = __expf(sacc[t][0] - mn0); s0 += sacc[t][0];
            sacc[t][1] = __expf(sacc[t][1] - mn0); s0 += sacc[t][1];
            sacc[t][2] = __expf(sacc[t][2] - mn1); s1 += sacc[t][2];
            sacc[t][3] = __expf(sacc[t][3] - mn1); s1 += sacc[t][3];
        }
        s0 += __shfl_xor_sync(0xffffffffu, s0, 1);
        s0 += __shfl_xor_sync(0xffffffffu, s0, 2);
        s1 += __shfl_xor_sync(0xffffffffu, s1, 1);
        s1 += __shfl_xor_sync(0xffffffffu, s1, 2);
        l0 = l0 * a0 + s0;
        l1 = l1 * a1 + s1;
#pragma unroll
        for (int j = 0; j < 8; j++) {
            oacc[j][0] *= a0; oacc[j][1] *= a0;
            oacc[j][2] *= a1; oacc[j][3] *= a1;
        }

        // ---- O += P @ V (bf16x3), P packed from S accumulators ----
#pragma unroll
        for (int s = 0; s < 4; s++) {
            uint32_t ah[4], al[4];
            pack_split(sacc[2 * s][0],     sacc[2 * s][1],     ah[0], al[0]);
            pack_split(sacc[2 * s][2],     sacc[2 * s][3],     ah[1], al[1]);
            pack_split(sacc[2 * s + 1][0], sacc[2 * s + 1][1], ah[2], al[2]);
            pack_split(sacc[2 * s + 1][2], sacc[2 * s + 1][3], ah[3], al[3]);
            uint32_t vbh[4][4], vbl[4][4];
#pragma unroll
            for (int J = 0; J < 4; J++) {
                int r = 16 * s + (lane & 7) + ((lane >> 3) & 1) * 8;
                int c = 2 * J + (lane >> 4);
                ldm_x4_t(vbh[J], stg + 16384 + FSWZ(r, c));
                ldm_x4_t(vbl[J], stg + 24576 + FSWZ(r, c));
            }
#pragma unroll
            for (int j = 0; j < 8; j++) {
                const int J = j >> 1, hf = (j & 1) * 2;
                mma16816(oacc[j], ah, &vbh[J][hf]);
                mma16816(oacc[j], ah, &vbl[J][hf]);
                mma16816(oacc[j], al, &vbh[J][hf]);
            }
        }

        __syncthreads();
        if (kc + 2 < FA_NC) { load_kv(kc & 1, kc + 2); cp_commit(); }
    }

    // ---- normalize + write O (bf16 hi/lo split) ----
    float inv0 = 1.f / l0, inv1 = 1.f / l1;
    int r = lane >> 2;
    size_t row0 = (size_t)(b * SEQ + qt * FA_BQ + wid * 16 + r);
    size_t row1 = row0 + 8;
    int colb = h * DHEAD + (lane & 3) * 2;
#pragma unroll
    for (int j = 0; j < 8; j++) {
        size_t o0 = row0 * INNER + colb + j * 8;
        size_t o1 = row1 * INNER + colb + j * 8;
        uint32_t h0, lo0, h1, lo1;
        pack_split(oacc[j][0] * inv0, oacc[j][1] * inv0, h0, lo0);
        pack_split(oacc[j][2] * inv1, oacc[j][3] * inv1, h1, lo1);
        *(uint32_t*)(Oh + o0) = h0;
        *(uint32_t*)(Ol + o0) = lo0;
        *(uint32_t*)(Oh + o1) = h1;
        *(uint32_t*)(Ol + o1) = lo1;
    }
}

// ---------------------------------------------------------------------------
extern "C" void kernel_launch(void* const* d_in, const int* in_sizes, int n_in,
                              void* d_out, int out_size)
{
    const float* x   = (const float*)d_in[0];
    const float* Wq  = (const float*)d_in[1];
    const float* Wkv = (const float*)d_in[2];
    const float* Wo  = (const float*)d_in[3];
    const float* bo  = (const float*)d_in[4];
    float* out = (float*)d_out;

    __nv_bfloat16 *xh, *xl, *qh, *ql, *kh, *kl, *vh, *vl, *oh, *ol;
    __nv_bfloat16 *wqth, *wqtl, *wkvth, *wkvtl, *woth, *wotl;
    cudaGetSymbolAddress((void**)&xh, g_xh);
    cudaGetSymbolAddress((void**)&xl, g_xl);
    cudaGetSymbolAddress((void**)&qh, g_qh);
    cudaGetSymbolAddress((void**)&ql, g_ql);
    cudaGetSymbolAddress((void**)&kh, g_kh);
    cudaGetSymbolAddress((void**)&kl, g_kl);
    cudaGetSymbolAddress((void**)&vh, g_vh);
    cudaGetSymbolAddress((void**)&vl, g_vl);
    cudaGetSymbolAddress((void**)&oh, g_oh);
    cudaGetSymbolAddress((void**)&ol, g_ol);
    cudaGetSymbolAddress((void**)&wqth, g_wqth);
    cudaGetSymbolAddress((void**)&wqtl, g_wqtl);
    cudaGetSymbolAddress((void**)&wkvth, g_wkvth);
    cudaGetSymbolAddress((void**)&wkvtl, g_wkvtl);
    cudaGetSymbolAddress((void**)&woth, g_woth);
    cudaGetSymbolAddress((void**)&wotl, g_wotl);

    cudaFuncSetAttribute(gemm_tc, cudaFuncAttributeMaxDynamicSharedMemorySize, HT_SMEM);
    cudaFuncSetAttribute(flash_tc, cudaFuncAttributeMaxDynamicSharedMemorySize, FA_SMEM);

    // prep
    split_x_kernel<<<TOKENS * DIM / (256 * 4), 256>>>(x, xh, xl);
    transpose_split_kernel<<<dim3(DIM / 32, INNER / 32), dim3(32, 8)>>>(Wq, wqth, wqtl, DIM, INNER);
    transpose_split_kernel<<<dim3(DIM / 32, 2 * INNER / 32), dim3(32, 8)>>>(Wkv, wkvth, wkvtl, DIM, 2 * INNER);
    transpose_split_kernel<<<dim3(INNER / 32, DIM / 32), dim3(32, 8)>>>(Wo, woth, wotl, INNER, DIM);

    // q = (x @ Wq) * ATT_SCALE   -> bf16 split
    gemm_tc<<<dim3(INNER / 128, TOKENS / 128), 256, HT_SMEM>>>(
        xh, xl, wqth, wqtl, nullptr, nullptr, qh, ql, nullptr, nullptr,
        INNER, nullptr, ATT_SCALE, INNER, DIM);
    // [k | v] = x @ Wkv          -> bf16 split (k to C0, v to C1)
    gemm_tc<<<dim3(2 * INNER / 128, TOKENS / 128), 256, HT_SMEM>>>(
        xh, xl, wkvth, wkvtl, nullptr, nullptr, kh, kl, vh, vl,
        INNER, nullptr, 1.0f, 2 * INNER, DIM);
    // attention on tensor cores
    flash_tc<<<dim3(SEQ / FA_BQ, BATCH * HEADS), 256, FA_SMEM>>>(
        qh, ql, kh, kl, vh, vl, oh, ol);
    // out = O @ Wo + bo          -> fp32
    gemm_tc<<<dim3(DIM / 128, TOKENS / 128), 256, HT_SMEM>>>(
        oh, ol, woth, wotl, out, nullptr, nullptr, nullptr, nullptr, nullptr,
        DIM, bo, 1.0f, DIM, INNER);
}